// round 5
// baseline (speedup 1.0000x reference)
#include <cuda_runtime.h>
#include <cuda_fp16.h>
#include <cstdint>

// ---------------- problem constants ----------------
#define TOKENS   32768
#define HIDDEN   5120
#define NEXP     160
#define NGROUP   8
#define EPG      20
#define TOPK     6
#define KCHUNK   64
#define NCHUNKS  (HIDDEN / KCHUNK)   // 80
#define MTILE    64
#define NTHREADS 256

// scales: ra*2^15 * w*2^10 == x*2^4 * sb*2^21 == product * 2^25
#define S_RA 32768.0f
#define S_X  16.0f
#define S_W  1024.0f
#define S_SB 2097152.0f
#define INV25 2.9802322387695312e-8f   // 2^-25

// ---------------- smem layout ----------------
// A fp16: buf(2) x [64 x 128B] = 16384 ; A int8: buf(2) x [64 x 128B] = 16384
// B fp16: buf(2) x [160 x 128B] = 40960 ; B int8: buf(2) x [160 x 128B] = 40960
#define SA16(buf) ((buf) * 8192)
#define SAQ(buf)  (16384 + (buf) * 8192)
#define SB16(buf) (32768 + (buf) * 20480)
#define SBQ(buf)  (73728 + (buf) * 20480)
#define SMEM_BYTES 114688
#define BTILE_BYTES 20480
#define EPI_STRIDE 162
#define RED_OFF 49152      // 4 x 64 floats (overlays B16 region, post-sync)
#define G8_OFF  50176      // 8 x 64 floats

#define SWZ(o) ((uint32_t)(o) ^ (((uint32_t)(o) >> 3) & 0x70))

// ---------------- device scratch: prepped W tiles ---------------------------
__device__ __align__(16) unsigned char g_whF[NCHUNKS * BTILE_BYTES];  // fp16 w
__device__ __align__(16) unsigned char g_wq[NCHUNKS * BTILE_BYTES];   // [w8|sb8]

// ---------------- helpers ----------------
__device__ __forceinline__ uint32_t smem_u32(const void* p) {
    uint32_t a;
    asm("{ .reg .u64 t; cvta.to.shared.u64 t, %1; cvt.u32.u64 %0, t; }"
        : "=r"(a) : "l"(p));
    return a;
}

__device__ __forceinline__ uint32_t h2_bits(__half2 h) {
    return *reinterpret_cast<uint32_t*>(&h);
}

__device__ __forceinline__ uint32_t pack4s8(int i0, int i1, int i2, int i3) {
    uint32_t t0 = __byte_perm((uint32_t)i0, (uint32_t)i1, 0x0040);
    uint32_t t1 = __byte_perm((uint32_t)i2, (uint32_t)i3, 0x0040);
    return __byte_perm(t0, t1, 0x5410);
}

#define LDSM_X4(r0, r1, r2, r3, addr) \
    asm volatile("ldmatrix.sync.aligned.m8n8.x4.shared.b16 {%0,%1,%2,%3}, [%4];" \
                 : "=r"(r0), "=r"(r1), "=r"(r2), "=r"(r3) : "r"(addr))

#define LDSM_X2(r0, r1, addr) \
    asm volatile("ldmatrix.sync.aligned.m8n8.x2.shared.b16 {%0,%1}, [%2];" \
                 : "=r"(r0), "=r"(r1) : "r"(addr))

#define MMA16816(d, a0, a1, a2, a3, b0, b1) \
    asm volatile("mma.sync.aligned.m16n8k16.row.col.f32.f16.f16.f32 " \
                 "{%0,%1,%2,%3}, {%4,%5,%6,%7}, {%8,%9}, {%0,%1,%2,%3};" \
                 : "+f"((d)[0]), "+f"((d)[1]), "+f"((d)[2]), "+f"((d)[3]) \
                 : "r"(a0), "r"(a1), "r"(a2), "r"(a3), "r"(b0), "r"(b1))

#define MMAI8(d, a0, a1, a2, a3, b0, b1) \
    asm volatile("mma.sync.aligned.m16n8k32.row.col.s32.s8.s8.s32 " \
                 "{%0,%1,%2,%3}, {%4,%5,%6,%7}, {%8,%9}, {%0,%1,%2,%3};" \
                 : "+r"((d)[0]), "+r"((d)[1]), "+r"((d)[2]), "+r"((d)[3]) \
                 : "r"(a0), "r"(a1), "r"(a2), "r"(a3), "r"(b0), "r"(b1))

#define CP_ASYNC16(saddr, gptr) \
    asm volatile("cp.async.cg.shared.global [%0], [%1], 16;" \
                 :: "r"(saddr), "l"(gptr))
#define CP_COMMIT() asm volatile("cp.async.commit_group;" ::: "memory")
#define CP_WAIT0()  asm volatile("cp.async.wait_group 0;" ::: "memory")

// ---------------- prep: W -> fp16 tile + int8 [w8|sb8] tile ----------------
__global__ void prep_w_kernel(const float* __restrict__ w) {
    int idx = blockIdx.x * 256 + threadIdx.x;
    if (idx >= NEXP * (HIDDEN / 8)) return;
    int n  = idx / (HIDDEN / 8);
    int k8 = idx - n * (HIDDEN / 8);
    int k  = k8 * 8;
    const float4* src = reinterpret_cast<const float4*>(w + (size_t)n * HIDDEN + k);
    float4 v0 = src[0], v1 = src[1];
    float f[8] = {v0.x, v0.y, v0.z, v0.w, v1.x, v1.y, v1.z, v1.w};

    uint32_t hh[4];
    int w8[8], s8[8];
#pragma unroll
    for (int i = 0; i < 4; ++i) {
        __half2 h = __floats2half2_rn(f[2 * i], f[2 * i + 1]);
        hh[i] = h2_bits(h);
        float2 hf = __half22float2(h);
        w8[2 * i]     = __float2int_rn(f[2 * i] * S_W);
        w8[2 * i + 1] = __float2int_rn(f[2 * i + 1] * S_W);
        s8[2 * i]     = __float2int_rn((f[2 * i] - hf.x) * S_SB);
        s8[2 * i + 1] = __float2int_rn((f[2 * i + 1] - hf.y) * S_SB);
    }

    int c   = k >> 6;
    int col = k & 63;
    // fp16 tile: 128B rows of 64 fp16
    *reinterpret_cast<uint4*>(g_whF + (size_t)c * BTILE_BYTES + SWZ(n * 128 + col * 2)) =
        make_uint4(hh[0], hh[1], hh[2], hh[3]);
    // int8 tile: 128B rows = [w8 k0..63 | sb8 k0..63]
    *reinterpret_cast<uint2*>(g_wq + (size_t)c * BTILE_BYTES + SWZ(n * 128 + col)) =
        make_uint2(pack4s8(w8[0], w8[1], w8[2], w8[3]),
                   pack4s8(w8[4], w8[5], w8[6], w8[7]));
    *reinterpret_cast<uint2*>(g_wq + (size_t)c * BTILE_BYTES + SWZ(n * 128 + 64 + col)) =
        make_uint2(pack4s8(s8[0], s8[1], s8[2], s8[3]),
                   pack4s8(s8[4], s8[5], s8[6], s8[7]));
}

// ---------------- A chunk convert+store (fp16 + int8 tiles) ----------------
__device__ __forceinline__ void store_a(char* smem, int sa16, int saq,
                                        const float4* xv, const uint32_t* sts16,
                                        const uint32_t* stsq0, const uint32_t* stsq1) {
#pragma unroll
    for (int it = 0; it < 4; ++it) {
        float4 v = xv[it];
        __half2 h01 = __floats2half2_rn(v.x, v.y);
        __half2 h23 = __floats2half2_rn(v.z, v.w);
        *reinterpret_cast<uint2*>(smem + sa16 + sts16[it]) =
            make_uint2(h2_bits(h01), h2_bits(h23));
        float2 f01 = __half22float2(h01);
        float2 f23 = __half22float2(h23);
        int r0 = __float2int_rn((v.x - f01.x) * S_RA);
        int r1 = __float2int_rn((v.y - f01.y) * S_RA);
        int r2 = __float2int_rn((v.z - f23.x) * S_RA);
        int r3 = __float2int_rn((v.w - f23.y) * S_RA);
        int x0 = __float2int_rn(v.x * S_X);
        int x1 = __float2int_rn(v.y * S_X);
        int x2 = __float2int_rn(v.z * S_X);
        int x3 = __float2int_rn(v.w * S_X);
        *reinterpret_cast<uint32_t*>(smem + saq + stsq0[it]) = pack4s8(r0, r1, r2, r3);
        *reinterpret_cast<uint32_t*>(smem + saq + stsq1[it]) = pack4s8(x0, x1, x2, x3);
    }
}

// ---------------- main fused kernel ----------------------------------------
__global__ __launch_bounds__(NTHREADS, 1)
void moe_gate_kernel(const float* __restrict__ x, float* __restrict__ out) {
    extern __shared__ __align__(1024) char smem[];
    const uint32_t sb = smem_u32(smem);
    const int tid  = threadIdx.x;
    const int lane = tid & 31;
    const int wid  = tid >> 5;
    const int wm   = wid >> 2;
    const int wn   = wid & 3;
    const int m0   = blockIdx.x * MTILE;

    const int g  = tid & 15;
    const int rg = tid >> 4;
    const float* xbase = x + (size_t)(m0 + rg) * HIDDEN + g * 4;

    uint32_t sts16[4], stsq0[4], stsq1[4];
#pragma unroll
    for (int it = 0; it < 4; ++it) {
        int row = rg + it * 16;
        sts16[it] = (uint32_t)(row * 128) + (((uint32_t)(g * 8)) ^ ((uint32_t)(row & 7) << 4));
        stsq0[it] = SWZ(row * 128 + g * 4);
        stsq1[it] = SWZ(row * 128 + 64 + g * 4);
    }

    const int grp = lane >> 3;
    const int lr  = lane & 7;

    uint32_t a_row_off[2], a_swm[2];
#pragma unroll
    for (int mi = 0; mi < 2; ++mi) {
        int row = wm * 32 + mi * 16 + (grp & 1) * 8 + lr;
        a_row_off[mi] = (uint32_t)(row * 128);
        a_swm[mi]     = (uint32_t)(row & 7) << 4;
    }
    const int a_segadd = (grp >> 1);

    uint32_t b_row_off[2], b_swm[2];
#pragma unroll
    for (int p = 0; p < 2; ++p) {
        int n = wn * 40 + p * 16 + (grp >> 1) * 8 + lr;
        b_row_off[p] = (uint32_t)(n * 128);
        b_swm[p]     = (uint32_t)(n & 7) << 4;
    }
    const int b_segadd = (grp & 1);
    int n2 = wn * 40 + 32 + ((lane & 15) & 7);
    const uint32_t b2_row_off = (uint32_t)(n2 * 128);
    const uint32_t b2_swm     = (uint32_t)(n2 & 7) << 4;
    const int b2_segadd = ((lane & 15) >> 3);

    float acc[2][5][4];
    int   iacc[2][5][4];
#pragma unroll
    for (int mi = 0; mi < 2; ++mi)
#pragma unroll
        for (int nj = 0; nj < 5; ++nj)
#pragma unroll
            for (int q = 0; q < 4; ++q) { acc[mi][nj][q] = 0.f; iacc[mi][nj][q] = 0; }

    float4 xv[4];

    // ---------------- prologue: stage chunk 0 ----------------
    {
#pragma unroll
        for (int i = 0; i < 5; ++i) {
            uint32_t o = (uint32_t)(i * 256 + tid) * 16;
            CP_ASYNC16(sb + SB16(0) + o, g_whF + o);
            CP_ASYNC16(sb + SBQ(0) + o, g_wq + o);
        }
        CP_COMMIT();
#pragma unroll
        for (int it = 0; it < 4; ++it)
            xv[it] = *reinterpret_cast<const float4*>(xbase + (size_t)(it * 16) * HIDDEN);
        store_a(smem, SA16(0), SAQ(0), xv, sts16, stsq0, stsq1);
        CP_WAIT0();
        __syncthreads();
    }

    // ---------------- main loop ----------------
    int buf = 0;
    for (int c = 0; c < NCHUNKS; ++c) {
        const bool more = (c + 1 < NCHUNKS);
        if (more) {
            const size_t bo = (size_t)(c + 1) * BTILE_BYTES;
#pragma unroll
            for (int i = 0; i < 5; ++i) {
                uint32_t o = (uint32_t)(i * 256 + tid) * 16;
                CP_ASYNC16(sb + SB16(buf ^ 1) + o, g_whF + bo + o);
                CP_ASYNC16(sb + SBQ(buf ^ 1) + o, g_wq + bo + o);
            }
            CP_COMMIT();
            const float* xc = xbase + (size_t)(c + 1) * KCHUNK;
#pragma unroll
            for (int it = 0; it < 4; ++it)
                xv[it] = *reinterpret_cast<const float4*>(xc + (size_t)(it * 16) * HIDDEN);
        }

        const uint32_t a16 = sb + SA16(buf);
        const uint32_t aQ  = sb + SAQ(buf);
        const uint32_t b16 = sb + SB16(buf);
        const uint32_t bQ  = sb + SBQ(buf);
#pragma unroll
        for (int s = 0; s < 4; ++s) {
            uint32_t bh[10], bq[10];
#pragma unroll
            for (int p = 0; p < 2; ++p) {
                uint32_t seg = (uint32_t)(2 * s + b_segadd) << 4;
                uint32_t off = b_row_off[p] + (seg ^ b_swm[p]);
                LDSM_X4(bh[4 * p + 0], bh[4 * p + 1], bh[4 * p + 2], bh[4 * p + 3], b16 + off);
                LDSM_X4(bq[4 * p + 0], bq[4 * p + 1], bq[4 * p + 2], bq[4 * p + 3], bQ + off);
            }
            {
                uint32_t seg = (uint32_t)(2 * s + b2_segadd) << 4;
                uint32_t off = b2_row_off + (seg ^ b2_swm);
                LDSM_X2(bh[8], bh[9], b16 + off);
                LDSM_X2(bq[8], bq[9], bQ + off);
            }
#pragma unroll
            for (int mi = 0; mi < 2; ++mi) {
                uint32_t seg = (uint32_t)(2 * s + a_segadd) << 4;
                uint32_t off = a_row_off[mi] + (seg ^ a_swm[mi]);
                uint32_t a0, a1, a2, a3, q0, q1, q2, q3;
                LDSM_X4(a0, a1, a2, a3, a16 + off);
                LDSM_X4(q0, q1, q2, q3, aQ + off);
#pragma unroll
                for (int nj = 0; nj < 5; ++nj) {
                    MMA16816(acc[mi][nj], a0, a1, a2, a3, bh[2 * nj], bh[2 * nj + 1]);
                    MMAI8(iacc[mi][nj], q0, q1, q2, q3, bq[2 * nj], bq[2 * nj + 1]);
                }
            }
        }

        if (more) {
            store_a(smem, SA16(buf ^ 1), SAQ(buf ^ 1), xv, sts16, stsq0, stsq1);
            CP_WAIT0();
        }
        __syncthreads();
        buf ^= 1;
    }

    // ---------------- accs -> smem (recombined logits) ----------------------
    float* lg = reinterpret_cast<float*>(smem);
#pragma unroll
    for (int mi = 0; mi < 2; ++mi) {
        int r0 = wm * 32 + mi * 16 + (lane >> 2);
#pragma unroll
        for (int nj = 0; nj < 5; ++nj) {
            int cb = wn * 40 + nj * 8 + (lane & 3) * 2;
            *reinterpret_cast<float2*>(lg + (size_t)r0 * EPI_STRIDE + cb) =
                make_float2(acc[mi][nj][0] + (float)iacc[mi][nj][0] * INV25,
                            acc[mi][nj][1] + (float)iacc[mi][nj][1] * INV25);
            *reinterpret_cast<float2*>(lg + (size_t)(r0 + 8) * EPI_STRIDE + cb) =
                make_float2(acc[mi][nj][2] + (float)iacc[mi][nj][2] * INV25,
                            acc[mi][nj][3] + (float)iacc[mi][nj][3] * INV25);
        }
    }
    __syncthreads();

    // ---------------- epilogue: 4 threads per token, 40 experts each -------
    float* red = reinterpret_cast<float*>(smem + RED_OFF);   // [4][64]
    float* g8  = reinterpret_cast<float*>(smem + G8_OFF);    // [8][64]
    {
        const int tok = tid & 63;
        const int seg = tid >> 6;
        const int e0  = seg * 40;

        float z[40];
#pragma unroll
        for (int j = 0; j < 40; j += 2) {
            float2 v = *reinterpret_cast<float2*>(lg + (size_t)tok * EPI_STRIDE + e0 + j);
            z[j] = v.x; z[j + 1] = v.y;
        }

        float mx = -3.4e38f;
#pragma unroll
        for (int j = 0; j < 40; ++j) mx = fmaxf(mx, z[j]);
        red[seg * 64 + tok] = mx;
        __syncthreads();
        mx = fmaxf(fmaxf(red[tok], red[64 + tok]), fmaxf(red[128 + tok], red[192 + tok]));
        __syncthreads();

        float sum = 0.f;
#pragma unroll
        for (int j = 0; j < 40; ++j) {
            float p = __expf(z[j] - mx);
            sum += p;
            z[j] = p;
        }
        red[seg * 64 + tok] = sum;
        __syncthreads();
        sum = (red[tok] + red[64 + tok]) + (red[128 + tok] + red[192 + tok]);

        float gm0 = 0.f, gm1 = 0.f;
#pragma unroll
        for (int j = 0; j < 20; ++j) gm0 = fmaxf(gm0, z[j]);
#pragma unroll
        for (int j = 20; j < 40; ++j) gm1 = fmaxf(gm1, z[j]);
        g8[(2 * seg) * 64 + tok]     = gm0;
        g8[(2 * seg + 1) * 64 + tok] = gm1;
        __syncthreads();

        float gv[NGROUP];
#pragma unroll
        for (int q = 0; q < NGROUP; ++q) gv[q] = g8[q * 64 + tok];
        float t1 = 0.f, t2 = 0.f, t3 = 0.f;
#pragma unroll
        for (int q = 0; q < NGROUP; ++q) t1 = fmaxf(t1, gv[q]);
#pragma unroll
        for (int q = 0; q < NGROUP; ++q) t2 = fmaxf(t2, (gv[q] < t1) ? gv[q] : 0.f);
#pragma unroll
        for (int q = 0; q < NGROUP; ++q) t3 = fmaxf(t3, (gv[q] < t2) ? gv[q] : 0.f);

        float keep0 = (gm0 >= t3) ? 1.f : 0.f;
        float keep1 = (gm1 >= t3) ? 1.f : 0.f;
#pragma unroll
        for (int j = 0; j < 20; ++j) z[j] *= keep0;
#pragma unroll
        for (int j = 20; j < 40; ++j) z[j] *= keep1;

        const float inv = 16.0f / sum;
        float* orow = out + (size_t)(m0 + tok) * TOPK;
        float prev = 3.4e38f;
        __syncthreads();
        for (int i = 0; i < TOPK; ++i) {
            float cand = 0.f;
#pragma unroll
            for (int j = 0; j < 40; ++j)
                cand = fmaxf(cand, (z[j] < prev) ? z[j] : 0.f);
            red[seg * 64 + tok] = cand;
            __syncthreads();
            float cur = fmaxf(fmaxf(red[tok], red[64 + tok]),
                              fmaxf(red[128 + tok], red[192 + tok]));
            __syncthreads();
            if (seg == 0) orow[i] = cur * inv;
            prev = cur;
        }
    }
}

// ---------------- launch ----------------------------------------------------
extern "C" void kernel_launch(void* const* d_in, const int* in_sizes, int n_in,
                              void* d_out, int out_size) {
    const float* x = (const float*)d_in[0];   // [32768, 5120] fp32
    const float* w = (const float*)d_in[1];   // [160, 5120] fp32
    float* out = (float*)d_out;               // [32768, 6] fp32

    cudaFuncSetAttribute(moe_gate_kernel,
                         cudaFuncAttributeMaxDynamicSharedMemorySize, SMEM_BYTES);

    int prep_elems = NEXP * (HIDDEN / 8);
    prep_w_kernel<<<(prep_elems + 255) / 256, 256>>>(w);
    moe_gate_kernel<<<TOKENS / MTILE, NTHREADS, SMEM_BYTES>>>(x, out);
}

// round 6
// speedup vs baseline: 2.7498x; 2.7498x over previous
#include <cuda_runtime.h>
#include <cuda_fp16.h>
#include <cstdint>

// ---------------- problem constants ----------------
#define TOKENS   32768
#define HIDDEN   5120
#define NEXP     160
#define NGROUP   8
#define EPG      20
#define TOPK     6
#define KCHUNK   64
#define NCHUNKS  (HIDDEN / KCHUNK)   // 80
#define MTILE    128
#define NTHREADS 256
#define LO_SCALE 2048.0f             // 2^11
#define LO_INV   (1.0f / 2048.0f)

// ---------------- smem layout ----------------
// A: buf(2) x hi/lo(2) x [128 x 128B] = 4 x 16384 = 65536
// B: buf(2) x hi/lo(2) x [160 x 128B] = 4 x 20480 = 81920
#define SA_OFF(buf, hl) ((buf) * 32768 + (hl) * 16384)
#define SB_OFF(buf, hl) (65536 + (buf) * 40960 + (hl) * 20480)
#define SMEM_BYTES 147456
#define BTILE_BYTES 20480
#define EPI_STRIDE 162          // 128 rows x 162 f32 = 82944 B
#define RED_OFF 86016           // 2 x 128 floats
#define G8_OFF  87040           // 8 x 128 floats

#define SWZ(o) ((uint32_t)(o) ^ (((uint32_t)(o) >> 3) & 0x70))

// ---------------- device scratch: prepped W (fp16 hi + scaled fp16 lo) -----
__device__ __align__(16) unsigned char g_whi[NCHUNKS * BTILE_BYTES];
__device__ __align__(16) unsigned char g_wlo[NCHUNKS * BTILE_BYTES];

// ---------------- helpers ----------------
__device__ __forceinline__ uint32_t smem_u32(const void* p) {
    uint32_t a;
    asm("{ .reg .u64 t; cvta.to.shared.u64 t, %1; cvt.u32.u64 %0, t; }"
        : "=r"(a) : "l"(p));
    return a;
}

__device__ __forceinline__ uint32_t h2_bits(__half2 h) {
    return *reinterpret_cast<uint32_t*>(&h);
}

#define LDSM_X4(r0, r1, r2, r3, addr) \
    asm volatile("ldmatrix.sync.aligned.m8n8.x4.shared.b16 {%0,%1,%2,%3}, [%4];" \
                 : "=r"(r0), "=r"(r1), "=r"(r2), "=r"(r3) : "r"(addr))

#define LDSM_X2(r0, r1, addr) \
    asm volatile("ldmatrix.sync.aligned.m8n8.x2.shared.b16 {%0,%1}, [%2];" \
                 : "=r"(r0), "=r"(r1) : "r"(addr))

// f32-accumulate fp16 MMA (main term)
#define MMA_F32(d, a0, a1, a2, a3, b0, b1) \
    asm volatile("mma.sync.aligned.m16n8k16.row.col.f32.f16.f16.f32 " \
                 "{%0,%1,%2,%3}, {%4,%5,%6,%7}, {%8,%9}, {%0,%1,%2,%3};" \
                 : "+f"((d)[0]), "+f"((d)[1]), "+f"((d)[2]), "+f"((d)[3]) \
                 : "r"(a0), "r"(a1), "r"(a2), "r"(a3), "r"(b0), "r"(b1))

// f16-accumulate fp16 MMA (correction terms)
#define MMA_F16(d, a0, a1, a2, a3, b0, b1) \
    asm volatile("mma.sync.aligned.m16n8k16.row.col.f16.f16.f16.f16 " \
                 "{%0,%1}, {%2,%3,%4,%5}, {%6,%7}, {%0,%1};" \
                 : "+r"((d)[0]), "+r"((d)[1]) \
                 : "r"(a0), "r"(a1), "r"(a2), "r"(a3), "r"(b0), "r"(b1))

#define CP_ASYNC16(saddr, gptr) \
    asm volatile("cp.async.cg.shared.global [%0], [%1], 16;" \
                 :: "r"(saddr), "l"(gptr))
#define CP_COMMIT() asm volatile("cp.async.commit_group;" ::: "memory")
#define CP_WAIT0()  asm volatile("cp.async.wait_group 0;" ::: "memory")

// ---------------- prep: W -> fp16 hi tile + fp16 (lo*2^11) tile ------------
__global__ void prep_w_kernel(const float* __restrict__ w) {
    int idx = blockIdx.x * 256 + threadIdx.x;
    if (idx >= NEXP * (HIDDEN / 8)) return;
    int n  = idx / (HIDDEN / 8);
    int k8 = idx - n * (HIDDEN / 8);
    int k  = k8 * 8;
    const float4* src = reinterpret_cast<const float4*>(w + (size_t)n * HIDDEN + k);
    float4 v0 = src[0], v1 = src[1];
    float f[8] = {v0.x, v0.y, v0.z, v0.w, v1.x, v1.y, v1.z, v1.w};

    uint32_t hh[4], ll[4];
#pragma unroll
    for (int i = 0; i < 4; ++i) {
        __half2 h = __floats2half2_rn(f[2 * i], f[2 * i + 1]);
        hh[i] = h2_bits(h);
        float2 hf = __half22float2(h);
        __half2 l = __floats2half2_rn((f[2 * i]     - hf.x) * LO_SCALE,
                                      (f[2 * i + 1] - hf.y) * LO_SCALE);
        ll[i] = h2_bits(l);
    }

    int c   = k >> 6;
    int col = k & 63;
    uint32_t sw = SWZ(n * 128 + col * 2);
    *reinterpret_cast<uint4*>(g_whi + (size_t)c * BTILE_BYTES + sw) =
        make_uint4(hh[0], hh[1], hh[2], hh[3]);
    *reinterpret_cast<uint4*>(g_wlo + (size_t)c * BTILE_BYTES + sw) =
        make_uint4(ll[0], ll[1], ll[2], ll[3]);
}

// ---------------- main fused kernel ----------------------------------------
__global__ __launch_bounds__(NTHREADS, 1)
void moe_gate_kernel(const float* __restrict__ x, float* __restrict__ out) {
    extern __shared__ __align__(1024) char smem[];
    const uint32_t sb = smem_u32(smem);
    const int tid  = threadIdx.x;
    const int lane = tid & 31;
    const int wid  = tid >> 5;
    const int wm   = wid >> 2;       // 0..1 : 64-row M half
    const int wn   = wid & 3;        // 0..3 : 40-expert N quarter
    const int m0   = blockIdx.x * MTILE;

    const int g  = tid & 15;         // float4 column (64 floats = 16 float4)
    const int rg = tid >> 4;         // 0..15 row phase
    const float* xbase = x + (size_t)(m0 + rg) * HIDDEN + g * 4;

    uint32_t sts_off[8];
#pragma unroll
    for (int it = 0; it < 8; ++it) {
        int row = rg + it * 16;
        sts_off[it] = (uint32_t)(row * 128) + (((uint32_t)(g * 8)) ^ ((uint32_t)(row & 7) << 4));
    }

    const int grp = lane >> 3;
    const int lr  = lane & 7;

    uint32_t a_row_off[4], a_swm[4];
#pragma unroll
    for (int mi = 0; mi < 4; ++mi) {
        int row = wm * 64 + mi * 16 + (grp & 1) * 8 + lr;
        a_row_off[mi] = (uint32_t)(row * 128);
        a_swm[mi]     = (uint32_t)(row & 7) << 4;
    }
    const int a_segadd = (grp >> 1);

    uint32_t b_row_off[2], b_swm[2];
#pragma unroll
    for (int p = 0; p < 2; ++p) {
        int n = wn * 40 + p * 16 + (grp >> 1) * 8 + lr;
        b_row_off[p] = (uint32_t)(n * 128);
        b_swm[p]     = (uint32_t)(n & 7) << 4;
    }
    const int b_segadd = (grp & 1);
    int n2 = wn * 40 + 32 + ((lane & 15) & 7);
    const uint32_t b2_row_off = (uint32_t)(n2 * 128);
    const uint32_t b2_swm     = (uint32_t)(n2 & 7) << 4;
    const int b2_segadd = ((lane & 15) >> 3);

    float    facc[4][5][4];   // main term, f32 acc
    uint32_t hacc[4][5][2];   // correction terms, f16 acc (half2 pairs)
#pragma unroll
    for (int mi = 0; mi < 4; ++mi)
#pragma unroll
        for (int nj = 0; nj < 5; ++nj) {
#pragma unroll
            for (int q = 0; q < 4; ++q) facc[mi][nj][q] = 0.f;
            hacc[mi][nj][0] = 0u; hacc[mi][nj][1] = 0u;
        }

    float4 xv[8];

    // ---------------- prologue: stage chunk 0 ----------------
    {
#pragma unroll
        for (int i = 0; i < 5; ++i) {
            uint32_t o = (uint32_t)(i * 256 + tid) * 16;
            CP_ASYNC16(sb + SB_OFF(0, 0) + o, g_whi + o);
            CP_ASYNC16(sb + SB_OFF(0, 1) + o, g_wlo + o);
        }
        CP_COMMIT();
#pragma unroll
        for (int it = 0; it < 8; ++it)
            xv[it] = *reinterpret_cast<const float4*>(xbase + (size_t)(it * 16) * HIDDEN);
#pragma unroll
        for (int it = 0; it < 8; ++it) {
            float4 v = xv[it];
            __half2 h01 = __floats2half2_rn(v.x, v.y);
            __half2 h23 = __floats2half2_rn(v.z, v.w);
            float2 f01 = __half22float2(h01);
            float2 f23 = __half22float2(h23);
            __half2 l01 = __floats2half2_rn((v.x - f01.x) * LO_SCALE, (v.y - f01.y) * LO_SCALE);
            __half2 l23 = __floats2half2_rn((v.z - f23.x) * LO_SCALE, (v.w - f23.y) * LO_SCALE);
            *reinterpret_cast<uint2*>(smem + SA_OFF(0, 0) + sts_off[it]) =
                make_uint2(h2_bits(h01), h2_bits(h23));
            *reinterpret_cast<uint2*>(smem + SA_OFF(0, 1) + sts_off[it]) =
                make_uint2(h2_bits(l01), h2_bits(l23));
        }
        CP_WAIT0();
        __syncthreads();
    }

    // ---------------- main loop ----------------
    int buf = 0;
    for (int c = 0; c < NCHUNKS; ++c) {
        const bool more = (c + 1 < NCHUNKS);
        if (more) {
            const size_t bo = (size_t)(c + 1) * BTILE_BYTES;
#pragma unroll
            for (int i = 0; i < 5; ++i) {
                uint32_t o = (uint32_t)(i * 256 + tid) * 16;
                CP_ASYNC16(sb + SB_OFF(buf ^ 1, 0) + o, g_whi + bo + o);
                CP_ASYNC16(sb + SB_OFF(buf ^ 1, 1) + o, g_wlo + bo + o);
            }
            CP_COMMIT();
            const float* xc = xbase + (size_t)(c + 1) * KCHUNK;
#pragma unroll
            for (int it = 0; it < 8; ++it)
                xv[it] = *reinterpret_cast<const float4*>(xc + (size_t)(it * 16) * HIDDEN);
        }

        const uint32_t aHi = sb + SA_OFF(buf, 0);
        const uint32_t aLo = sb + SA_OFF(buf, 1);
        const uint32_t bHi = sb + SB_OFF(buf, 0);
        const uint32_t bLo = sb + SB_OFF(buf, 1);
#pragma unroll
        for (int s = 0; s < 4; ++s) {
            uint32_t bh[10], bl[10];
#pragma unroll
            for (int p = 0; p < 2; ++p) {
                uint32_t seg = (uint32_t)(2 * s + b_segadd) << 4;
                uint32_t off = b_row_off[p] + (seg ^ b_swm[p]);
                LDSM_X4(bh[4 * p + 0], bh[4 * p + 1], bh[4 * p + 2], bh[4 * p + 3], bHi + off);
                LDSM_X4(bl[4 * p + 0], bl[4 * p + 1], bl[4 * p + 2], bl[4 * p + 3], bLo + off);
            }
            {
                uint32_t seg = (uint32_t)(2 * s + b2_segadd) << 4;
                uint32_t off = b2_row_off + (seg ^ b2_swm);
                LDSM_X2(bh[8], bh[9], bHi + off);
                LDSM_X2(bl[8], bl[9], bLo + off);
            }
#pragma unroll
            for (int mi = 0; mi < 4; ++mi) {
                uint32_t seg = (uint32_t)(2 * s + a_segadd) << 4;
                uint32_t off = a_row_off[mi] + (seg ^ a_swm[mi]);
                uint32_t ah0, ah1, ah2, ah3, al0, al1, al2, al3;
                LDSM_X4(ah0, ah1, ah2, ah3, aHi + off);
                LDSM_X4(al0, al1, al2, al3, aLo + off);
#pragma unroll
                for (int nj = 0; nj < 5; ++nj) {
                    MMA_F32(facc[mi][nj], ah0, ah1, ah2, ah3, bh[2 * nj], bh[2 * nj + 1]);
                    MMA_F16(hacc[mi][nj], ah0, ah1, ah2, ah3, bl[2 * nj], bl[2 * nj + 1]);
                    MMA_F16(hacc[mi][nj], al0, al1, al2, al3, bh[2 * nj], bh[2 * nj + 1]);
                }
            }
        }

        if (more) {
#pragma unroll
            for (int it = 0; it < 8; ++it) {
                float4 v = xv[it];
                __half2 h01 = __floats2half2_rn(v.x, v.y);
                __half2 h23 = __floats2half2_rn(v.z, v.w);
                float2 f01 = __half22float2(h01);
                float2 f23 = __half22float2(h23);
                __half2 l01 = __floats2half2_rn((v.x - f01.x) * LO_SCALE, (v.y - f01.y) * LO_SCALE);
                __half2 l23 = __floats2half2_rn((v.z - f23.x) * LO_SCALE, (v.w - f23.y) * LO_SCALE);
                *reinterpret_cast<uint2*>(smem + SA_OFF(buf ^ 1, 0) + sts_off[it]) =
                    make_uint2(h2_bits(h01), h2_bits(h23));
                *reinterpret_cast<uint2*>(smem + SA_OFF(buf ^ 1, 1) + sts_off[it]) =
                    make_uint2(h2_bits(l01), h2_bits(l23));
            }
            CP_WAIT0();
        }
        __syncthreads();
        buf ^= 1;
    }

    // ---------------- accs -> smem (recombined logits) ----------------------
    float* lg = reinterpret_cast<float*>(smem);
#pragma unroll
    for (int mi = 0; mi < 4; ++mi) {
        int r0 = wm * 64 + mi * 16 + (lane >> 2);
#pragma unroll
        for (int nj = 0; nj < 5; ++nj) {
            int cb = wn * 40 + nj * 8 + (lane & 3) * 2;
            float2 c0 = __half22float2(*reinterpret_cast<__half2*>(&hacc[mi][nj][0]));
            float2 c1 = __half22float2(*reinterpret_cast<__half2*>(&hacc[mi][nj][1]));
            *reinterpret_cast<float2*>(lg + (size_t)r0 * EPI_STRIDE + cb) =
                make_float2(facc[mi][nj][0] + c0.x * LO_INV,
                            facc[mi][nj][1] + c0.y * LO_INV);
            *reinterpret_cast<float2*>(lg + (size_t)(r0 + 8) * EPI_STRIDE + cb) =
                make_float2(facc[mi][nj][2] + c1.x * LO_INV,
                            facc[mi][nj][3] + c1.y * LO_INV);
        }
    }
    __syncthreads();

    // ---------------- epilogue: 2 threads per token, 80 experts each -------
    float* red = reinterpret_cast<float*>(smem + RED_OFF);   // [2][128]
    float* g8  = reinterpret_cast<float*>(smem + G8_OFF);    // [8][128]
    {
        const int tok = tid & 127;
        const int seg = tid >> 7;          // 0..1
        const int e0  = seg * 80;

        float z[80];
#pragma unroll
        for (int j = 0; j < 80; j += 2) {
            float2 v = *reinterpret_cast<float2*>(lg + (size_t)tok * EPI_STRIDE + e0 + j);
            z[j] = v.x; z[j + 1] = v.y;
        }

        float mx = -3.4e38f;
#pragma unroll
        for (int j = 0; j < 80; ++j) mx = fmaxf(mx, z[j]);
        red[seg * 128 + tok] = mx;
        __syncthreads();
        mx = fmaxf(red[tok], red[128 + tok]);
        __syncthreads();

        float sum = 0.f;
#pragma unroll
        for (int j = 0; j < 80; ++j) {
            float p = __expf(z[j] - mx);
            sum += p;
            z[j] = p;
        }
        red[seg * 128 + tok] = sum;
        __syncthreads();
        sum = red[tok] + red[128 + tok];

        // group maxima: each seg owns 4 groups of 20
        float gm[4];
#pragma unroll
        for (int q = 0; q < 4; ++q) {
            float m = 0.f;
#pragma unroll
            for (int t = 0; t < EPG; ++t) m = fmaxf(m, z[q * EPG + t]);
            gm[q] = m;
            g8[(seg * 4 + q) * 128 + tok] = m;
        }
        __syncthreads();

        float gv[NGROUP];
#pragma unroll
        for (int q = 0; q < NGROUP; ++q) gv[q] = g8[q * 128 + tok];
        float t1 = 0.f, t2 = 0.f, t3 = 0.f;
#pragma unroll
        for (int q = 0; q < NGROUP; ++q) t1 = fmaxf(t1, gv[q]);
#pragma unroll
        for (int q = 0; q < NGROUP; ++q) t2 = fmaxf(t2, (gv[q] < t1) ? gv[q] : 0.f);
#pragma unroll
        for (int q = 0; q < NGROUP; ++q) t3 = fmaxf(t3, (gv[q] < t2) ? gv[q] : 0.f);

#pragma unroll
        for (int q = 0; q < 4; ++q) {
            float keep = (gm[q] >= t3) ? 1.f : 0.f;
#pragma unroll
            for (int t = 0; t < EPG; ++t) z[q * EPG + t] *= keep;
        }

        const float inv = 16.0f / sum;
        float* orow = out + (size_t)(m0 + tok) * TOPK;
        float prev = 3.4e38f;
        __syncthreads();
        for (int i = 0; i < TOPK; ++i) {
            float cand = 0.f;
#pragma unroll
            for (int j = 0; j < 80; ++j)
                cand = fmaxf(cand, (z[j] < prev) ? z[j] : 0.f);
            red[seg * 128 + tok] = cand;
            __syncthreads();
            float cur = fmaxf(red[tok], red[128 + tok]);
            __syncthreads();
            if (seg == 0) orow[i] = cur * inv;
            prev = cur;
        }
    }
}

// ---------------- launch ----------------------------------------------------
extern "C" void kernel_launch(void* const* d_in, const int* in_sizes, int n_in,
                              void* d_out, int out_size) {
    const float* x = (const float*)d_in[0];   // [32768, 5120] fp32
    const float* w = (const float*)d_in[1];   // [160, 5120] fp32
    float* out = (float*)d_out;               // [32768, 6] fp32

    cudaFuncSetAttribute(moe_gate_kernel,
                         cudaFuncAttributeMaxDynamicSharedMemorySize, SMEM_BYTES);

    int prep_elems = NEXP * (HIDDEN / 8);
    prep_w_kernel<<<(prep_elems + 255) / 256, 256>>>(w);
    moe_gate_kernel<<<TOKENS / MTILE, NTHREADS, SMEM_BYTES>>>(x, out);
}